// round 15
// baseline (speedup 1.0000x reference)
#include <cuda_runtime.h>

// Problem constants (fixed shapes for SpNCN_Layer_81106162417854)
#define T_STEPS 800
#define BATCH   128
#define S_DIM   500
#define BS      (BATCH * S_DIM)          // 64000
#define M_ROWS  (T_STEPS * BATCH)        // 102400

#define DT     0.25
#define ALPHA_F ((float)(1.0 - DT / 10.0))
#define BETA_F  ((float)(1.0 - DT / 20.0))
#define KAPPA_F ((float)(1.0 - DT / 30.0))
#define THRESH_F 0.4f

// Scratch for total = input - error @ W^T  (205 MB)
__device__ float g_total[(size_t)T_STEPS * BATCH * S_DIM];

// ---------------------------------------------------------------------------
// Kernel 1: total[m,n] = inp[m,n] - sum_k err[m,k] * W[n,k]
// NUMERICS CONTRACT (validated bitwise R4-R12): per output element a serial
// ascending-k single-accumulator scalar FFMA chain; one final __fadd_rn.
// R9 core (best measured: ~1047us): BM=BN=128, BK=16, 256 thr, occ2,
// fragment double-buffering. New: inp epilogue values prefetched during the
// last K-iteration (pf[] regs are dead there).
// ---------------------------------------------------------------------------
#define BM 128
#define BN 128
#define BK 16
#define KMAIN 496            // 31 * 16
#define NITER 31

__global__ __launch_bounds__(256, 2) void gemm_total_kernel(
    const float* __restrict__ inp,
    const float* __restrict__ err,
    const float* __restrict__ W)
{
    __shared__ float As[2][BK][BM];   // As[buf][k][m]  (16 KB)
    __shared__ float Bs[2][BK][BN];   // Bs[buf][k][n]  (16 KB)

    const int bm = blockIdx.y * BM;
    const int bn = blockIdx.x * BN;
    const int t  = threadIdx.x;

    // ---- load mapping: 128 rows x 4 k-quads per operand, 2 quads/thread ----
    const int lrow = t & 127;         // tile row (m for A, n for B)
    const int lq   = t >> 7;          // 0 or 1; quads {lq, lq+2}

    const float* Ap = err + (size_t)(bm + lrow) * S_DIM;
    const int    bn_row = bn + lrow;
    const bool   bok = (bn_row < S_DIM);
    const float* Bp = W + (size_t)(bok ? bn_row : 0) * S_DIM;
    const float4 f4z = make_float4(0.f, 0.f, 0.f, 0.f);

    // ---- compute mapping: cx,ry in 0..15; fragments at +0 and +64 ----
    const int cx = t & 15;
    const int ry = t >> 4;
    const int r0 = ry * 4, r1 = ry * 4 + 64;
    const int c0 = cx * 4, c1 = cx * 4 + 64;

    float acc[8][8];
#pragma unroll
    for (int i = 0; i < 8; i++)
#pragma unroll
        for (int j = 0; j < 8; j++) acc[i][j] = 0.f;

    float4 pa[2], pb[2];
    float4 fa0[2], fa1[2], fb0[2], fb1[2];   // double-buffered fragments
    float4 ivp[8][2];                        // inp epilogue prefetch (last iter)

    // prime tile 0
#pragma unroll
    for (int q = 0; q < 2; q++) {
        const int qq = lq + 2 * q;
        pa[q] = *(const float4*)(Ap + qq * 4);
        pb[q] = bok ? *(const float4*)(Bp + qq * 4) : f4z;
    }
#pragma unroll
    for (int q = 0; q < 2; q++) {
        const int qq = lq + 2 * q;
        As[0][qq * 4 + 0][lrow] = pa[q].x;  As[0][qq * 4 + 1][lrow] = pa[q].y;
        As[0][qq * 4 + 2][lrow] = pa[q].z;  As[0][qq * 4 + 3][lrow] = pa[q].w;
        Bs[0][qq * 4 + 0][lrow] = pb[q].x;  Bs[0][qq * 4 + 1][lrow] = pb[q].y;
        Bs[0][qq * 4 + 2][lrow] = pb[q].z;  Bs[0][qq * 4 + 3][lrow] = pb[q].w;
    }
    __syncthreads();

    int cur = 0;
    for (int iter = 0; iter < NITER; iter++) {
        // global prefetch of next tile into registers
        if (iter < NITER - 1) {
            const int k0n = (iter + 1) * BK;
#pragma unroll
            for (int q = 0; q < 2; q++) {
                const int qq = lq + 2 * q;
                pa[q] = *(const float4*)(Ap + k0n + qq * 4);
                pb[q] = bok ? *(const float4*)(Bp + k0n + qq * 4) : f4z;
            }
        } else {
            // pf regs are dead in the last iteration: prefetch epilogue inp
#pragma unroll
            for (int i = 0; i < 8; i++) {
                const int m = bm + (i < 4 ? r0 + i : r1 + (i - 4));
                const float* ip = inp + (size_t)m * S_DIM;
#pragma unroll
                for (int jg = 0; jg < 2; jg++) {
                    const int n0 = bn + (jg == 0 ? c0 : c1);
                    ivp[i][jg] = (n0 < S_DIM) ? *(const float4*)(ip + n0) : f4z;
                }
            }
        }

        // software-pipelined compute over kk: load kk+1 fragments, then FMA kk
        fa0[0] = *(const float4*)&As[cur][0][r0];
        fa1[0] = *(const float4*)&As[cur][0][r1];
        fb0[0] = *(const float4*)&Bs[cur][0][c0];
        fb1[0] = *(const float4*)&Bs[cur][0][c1];
#pragma unroll
        for (int kk = 0; kk < BK; kk++) {
            const int cb = kk & 1, nb = cb ^ 1;
            if (kk < BK - 1) {
                fa0[nb] = *(const float4*)&As[cur][kk + 1][r0];
                fa1[nb] = *(const float4*)&As[cur][kk + 1][r1];
                fb0[nb] = *(const float4*)&Bs[cur][kk + 1][c0];
                fb1[nb] = *(const float4*)&Bs[cur][kk + 1][c1];
            }
            const float av[8] = {fa0[cb].x, fa0[cb].y, fa0[cb].z, fa0[cb].w,
                                 fa1[cb].x, fa1[cb].y, fa1[cb].z, fa1[cb].w};
            const float bv[8] = {fb0[cb].x, fb0[cb].y, fb0[cb].z, fb0[cb].w,
                                 fb1[cb].x, fb1[cb].y, fb1[cb].z, fb1[cb].w};
#pragma unroll
            for (int i = 0; i < 8; i++)
#pragma unroll
                for (int j = 0; j < 8; j++)
                    acc[i][j] = __fmaf_rn(av[i], bv[j], acc[i][j]);
        }

        if (iter < NITER - 1) {
            const int nxt = cur ^ 1;
#pragma unroll
            for (int q = 0; q < 2; q++) {
                const int qq = lq + 2 * q;
                As[nxt][qq * 4 + 0][lrow] = pa[q].x;  As[nxt][qq * 4 + 1][lrow] = pa[q].y;
                As[nxt][qq * 4 + 2][lrow] = pa[q].z;  As[nxt][qq * 4 + 3][lrow] = pa[q].w;
                Bs[nxt][qq * 4 + 0][lrow] = pb[q].x;  Bs[nxt][qq * 4 + 1][lrow] = pb[q].y;
                Bs[nxt][qq * 4 + 2][lrow] = pb[q].z;  Bs[nxt][qq * 4 + 3][lrow] = pb[q].w;
            }
            __syncthreads();
            cur = nxt;
        }
    }

    // ---- K tail: k = 496..499 (one float4 per row) ----
    __syncthreads();                           // everyone done reading cur
    if (t < 128) {
        float4 v = *(const float4*)(Ap + KMAIN);
        As[0][0][lrow] = v.x; As[0][1][lrow] = v.y;
        As[0][2][lrow] = v.z; As[0][3][lrow] = v.w;
    } else {
        float4 v = bok ? *(const float4*)(Bp + KMAIN) : f4z;
        Bs[0][0][lrow] = v.x; Bs[0][1][lrow] = v.y;
        Bs[0][2][lrow] = v.z; Bs[0][3][lrow] = v.w;
    }
    __syncthreads();
#pragma unroll
    for (int kk = 0; kk < 4; kk++) {
        float4 a0 = *(const float4*)&As[0][kk][r0];
        float4 a1 = *(const float4*)&As[0][kk][r1];
        float4 b0 = *(const float4*)&Bs[0][kk][c0];
        float4 b1 = *(const float4*)&Bs[0][kk][c1];
        const float av[8] = {a0.x, a0.y, a0.z, a0.w, a1.x, a1.y, a1.z, a1.w};
        const float bv[8] = {b0.x, b0.y, b0.z, b0.w, b1.x, b1.y, b1.z, b1.w};
#pragma unroll
        for (int i = 0; i < 8; i++)
#pragma unroll
            for (int j = 0; j < 8; j++)
                acc[i][j] = __fmaf_rn(av[i], bv[j], acc[i][j]);
    }

    // ---- epilogue: total = inp - acc (single rounded subtract), float4 IO ----
#pragma unroll
    for (int i = 0; i < 8; i++) {
        const int m = bm + (i < 4 ? r0 + i : r1 + (i - 4));
        float* op = g_total + (size_t)m * S_DIM;
#pragma unroll
        for (int jg = 0; jg < 2; jg++) {
            const int n0 = bn + (jg == 0 ? c0 : c1);
            if (n0 < S_DIM) {   // n0 % 4 == 0 and S_DIM % 4 == 0 -> all-or-none
                const float4 iv = ivp[i][jg];
                float4 ov;
                ov.x = __fadd_rn(iv.x, -acc[i][jg * 4 + 0]);
                ov.y = __fadd_rn(iv.y, -acc[i][jg * 4 + 1]);
                ov.z = __fadd_rn(iv.z, -acc[i][jg * 4 + 2]);
                ov.w = __fadd_rn(iv.w, -acc[i][jg * 4 + 3]);
                *(float4*)(op + n0) = ov;
            }
        }
    }
}

// ---------------------------------------------------------------------------
// Kernel 2: sequential scan over T; each thread owns TWO adjacent neurons
// (float2 IO). Software-pipelined: batch i+1's 16 loads issue before batch i's
// compute, keeping DRAM busy during the serial dependency chain.
// Per-lane math identical to validated scalar version (bitwise contract).
// ---------------------------------------------------------------------------
__global__ __launch_bounds__(64) void scan_kernel(
    float* __restrict__ spk_out,
    float* __restrict__ tr_out)
{
    const int p = blockIdx.x * blockDim.x + threadIdx.x;   // pair index
    if (p >= BS / 2) return;

    const float2* tp = (const float2*)g_total + p;
    float2* sp = (float2*)spk_out + p;
    float2* rp = (float2*)tr_out + p;
    const int STRIDE2 = BS / 2;                            // float2 elems per t

    float2 syn = make_float2(0.f, 0.f);
    float2 mem = make_float2(0.f, 0.f);
    float2 tr  = make_float2(0.f, 0.f);

    float2 tot[2][16];
#pragma unroll
    for (int i = 0; i < 16; i++)
        tot[0][i] = __ldcs(tp + (size_t)i * STRIDE2);      // prime batch 0

#pragma unroll 1
    for (int t0 = 0; t0 < T_STEPS; t0 += 16) {
        const int buf = (t0 >> 4) & 1, nbuf = buf ^ 1;

        // prefetch next batch (independent of compute below -> stays in flight)
        if (t0 + 16 < T_STEPS) {
#pragma unroll
            for (int i = 0; i < 16; i++)
                tot[nbuf][i] = __ldcs(tp + (size_t)(t0 + 16 + i) * STRIDE2);
        }

#pragma unroll
        for (int i = 0; i < 16; i++) {
            float2 spk;
            // lane x
            {
                const float reset = (__fadd_rn(mem.x, -THRESH_F) > 0.f) ? 1.f : 0.f;
                syn.x = __fmaf_rn(ALPHA_F, syn.x, tot[buf][i].x);
                mem.x = __fmul_rn(__fmaf_rn(BETA_F, mem.x, syn.x),
                                  __fadd_rn(1.f, -reset));
                spk.x = (__fadd_rn(mem.x, -THRESH_F) > 0.f) ? 1.f : 0.f;
                tr.x  = __fmaf_rn(KAPPA_F, tr.x, spk.x);
            }
            // lane y
            {
                const float reset = (__fadd_rn(mem.y, -THRESH_F) > 0.f) ? 1.f : 0.f;
                syn.y = __fmaf_rn(ALPHA_F, syn.y, tot[buf][i].y);
                mem.y = __fmul_rn(__fmaf_rn(BETA_F, mem.y, syn.y),
                                  __fadd_rn(1.f, -reset));
                spk.y = (__fadd_rn(mem.y, -THRESH_F) > 0.f) ? 1.f : 0.f;
                tr.y  = __fmaf_rn(KAPPA_F, tr.y, spk.y);
            }
            __stcs(sp + (size_t)(t0 + i) * STRIDE2, spk);
            __stcs(rp + (size_t)(t0 + i) * STRIDE2, tr);
        }
    }
}

// ---------------------------------------------------------------------------
extern "C" void kernel_launch(void* const* d_in, const int* in_sizes, int n_in,
                              void* d_out, int out_size)
{
    const float* inp = (const float*)d_in[0];   // input_signal [T, B, S]
    const float* err = (const float*)d_in[1];   // error_signal [T, B, S]
    const float* W   = (const float*)d_in[2];   // W_err [S, S]
    float* out = (float*)d_out;                 // [spks | traces]

    dim3 grid((S_DIM + BN - 1) / BN, M_ROWS / BM);   // (4, 800)
    gemm_total_kernel<<<grid, 256>>>(inp, err, W);

    scan_kernel<<<(BS / 2 + 63) / 64, 64>>>(out, out + (size_t)T_STEPS * BS);
}

// round 16
// speedup vs baseline: 1.1323x; 1.1323x over previous
#include <cuda_runtime.h>

// Problem constants (fixed shapes for SpNCN_Layer_81106162417854)
#define T_STEPS 800
#define BATCH   128
#define S_DIM   500
#define BS      (BATCH * S_DIM)          // 64000
#define M_ROWS  (T_STEPS * BATCH)        // 102400

#define DT     0.25
#define ALPHA_F ((float)(1.0 - DT / 10.0))
#define BETA_F  ((float)(1.0 - DT / 20.0))
#define KAPPA_F ((float)(1.0 - DT / 30.0))
#define THRESH_F 0.4f

// Scratch for total = input - error @ W^T  (205 MB)
__device__ float g_total[(size_t)T_STEPS * BATCH * S_DIM];

// ---------------------------------------------------------------------------
// Kernel 1: total[m,n] = inp[m,n] - sum_k err[m,k] * W[n,k]
// NUMERICS CONTRACT (validated bitwise R4-R15): per output element a serial
// ascending-k single-accumulator scalar FFMA chain; one final __fadd_rn.
// EXACT R9 core (best measured GEMM: ~1047us): BM=BN=128, BK=16, 256 thr,
// occ2, register fragment double-buffering. Do not add register pressure.
// ---------------------------------------------------------------------------
#define BM 128
#define BN 128
#define BK 16
#define KMAIN 496            // 31 * 16
#define NITER 31

__global__ __launch_bounds__(256, 2) void gemm_total_kernel(
    const float* __restrict__ inp,
    const float* __restrict__ err,
    const float* __restrict__ W)
{
    __shared__ float As[2][BK][BM];   // As[buf][k][m]  (16 KB)
    __shared__ float Bs[2][BK][BN];   // Bs[buf][k][n]  (16 KB)

    const int bm = blockIdx.y * BM;
    const int bn = blockIdx.x * BN;
    const int t  = threadIdx.x;

    // ---- load mapping: 128 rows x 4 k-quads per operand, 2 quads/thread ----
    const int lrow = t & 127;         // tile row (m for A, n for B)
    const int lq   = t >> 7;          // 0 or 1; quads {lq, lq+2}

    const float* Ap = err + (size_t)(bm + lrow) * S_DIM;
    const int    bn_row = bn + lrow;
    const bool   bok = (bn_row < S_DIM);
    const float* Bp = W + (size_t)(bok ? bn_row : 0) * S_DIM;
    const float4 f4z = make_float4(0.f, 0.f, 0.f, 0.f);

    // ---- compute mapping: cx,ry in 0..15; fragments at +0 and +64 ----
    const int cx = t & 15;
    const int ry = t >> 4;
    const int r0 = ry * 4, r1 = ry * 4 + 64;
    const int c0 = cx * 4, c1 = cx * 4 + 64;

    float acc[8][8];
#pragma unroll
    for (int i = 0; i < 8; i++)
#pragma unroll
        for (int j = 0; j < 8; j++) acc[i][j] = 0.f;

    float4 pa[2], pb[2];
    float4 fa0[2], fa1[2], fb0[2], fb1[2];   // double-buffered fragments

    // prime tile 0
#pragma unroll
    for (int q = 0; q < 2; q++) {
        const int qq = lq + 2 * q;
        pa[q] = *(const float4*)(Ap + qq * 4);
        pb[q] = bok ? *(const float4*)(Bp + qq * 4) : f4z;
    }
#pragma unroll
    for (int q = 0; q < 2; q++) {
        const int qq = lq + 2 * q;
        As[0][qq * 4 + 0][lrow] = pa[q].x;  As[0][qq * 4 + 1][lrow] = pa[q].y;
        As[0][qq * 4 + 2][lrow] = pa[q].z;  As[0][qq * 4 + 3][lrow] = pa[q].w;
        Bs[0][qq * 4 + 0][lrow] = pb[q].x;  Bs[0][qq * 4 + 1][lrow] = pb[q].y;
        Bs[0][qq * 4 + 2][lrow] = pb[q].z;  Bs[0][qq * 4 + 3][lrow] = pb[q].w;
    }
    __syncthreads();

    int cur = 0;
    for (int iter = 0; iter < NITER; iter++) {
        // global prefetch of next tile into registers
        if (iter < NITER - 1) {
            const int k0n = (iter + 1) * BK;
#pragma unroll
            for (int q = 0; q < 2; q++) {
                const int qq = lq + 2 * q;
                pa[q] = *(const float4*)(Ap + k0n + qq * 4);
                pb[q] = bok ? *(const float4*)(Bp + k0n + qq * 4) : f4z;
            }
        }

        // software-pipelined compute over kk: load kk+1 fragments, then FMA kk
        fa0[0] = *(const float4*)&As[cur][0][r0];
        fa1[0] = *(const float4*)&As[cur][0][r1];
        fb0[0] = *(const float4*)&Bs[cur][0][c0];
        fb1[0] = *(const float4*)&Bs[cur][0][c1];
#pragma unroll
        for (int kk = 0; kk < BK; kk++) {
            const int cb = kk & 1, nb = cb ^ 1;
            if (kk < BK - 1) {
                fa0[nb] = *(const float4*)&As[cur][kk + 1][r0];
                fa1[nb] = *(const float4*)&As[cur][kk + 1][r1];
                fb0[nb] = *(const float4*)&Bs[cur][kk + 1][c0];
                fb1[nb] = *(const float4*)&Bs[cur][kk + 1][c1];
            }
            const float av[8] = {fa0[cb].x, fa0[cb].y, fa0[cb].z, fa0[cb].w,
                                 fa1[cb].x, fa1[cb].y, fa1[cb].z, fa1[cb].w};
            const float bv[8] = {fb0[cb].x, fb0[cb].y, fb0[cb].z, fb0[cb].w,
                                 fb1[cb].x, fb1[cb].y, fb1[cb].z, fb1[cb].w};
#pragma unroll
            for (int i = 0; i < 8; i++)
#pragma unroll
                for (int j = 0; j < 8; j++)
                    acc[i][j] = __fmaf_rn(av[i], bv[j], acc[i][j]);
        }

        if (iter < NITER - 1) {
            const int nxt = cur ^ 1;
#pragma unroll
            for (int q = 0; q < 2; q++) {
                const int qq = lq + 2 * q;
                As[nxt][qq * 4 + 0][lrow] = pa[q].x;  As[nxt][qq * 4 + 1][lrow] = pa[q].y;
                As[nxt][qq * 4 + 2][lrow] = pa[q].z;  As[nxt][qq * 4 + 3][lrow] = pa[q].w;
                Bs[nxt][qq * 4 + 0][lrow] = pb[q].x;  Bs[nxt][qq * 4 + 1][lrow] = pb[q].y;
                Bs[nxt][qq * 4 + 2][lrow] = pb[q].z;  Bs[nxt][qq * 4 + 3][lrow] = pb[q].w;
            }
            __syncthreads();
            cur = nxt;
        }
    }

    // ---- K tail: k = 496..499 (one float4 per row) ----
    __syncthreads();                           // everyone done reading cur
    if (t < 128) {
        float4 v = *(const float4*)(Ap + KMAIN);
        As[0][0][lrow] = v.x; As[0][1][lrow] = v.y;
        As[0][2][lrow] = v.z; As[0][3][lrow] = v.w;
    } else {
        float4 v = bok ? *(const float4*)(Bp + KMAIN) : f4z;
        Bs[0][0][lrow] = v.x; Bs[0][1][lrow] = v.y;
        Bs[0][2][lrow] = v.z; Bs[0][3][lrow] = v.w;
    }
    __syncthreads();
#pragma unroll
    for (int kk = 0; kk < 4; kk++) {
        float4 a0 = *(const float4*)&As[0][kk][r0];
        float4 a1 = *(const float4*)&As[0][kk][r1];
        float4 b0 = *(const float4*)&Bs[0][kk][c0];
        float4 b1 = *(const float4*)&Bs[0][kk][c1];
        const float av[8] = {a0.x, a0.y, a0.z, a0.w, a1.x, a1.y, a1.z, a1.w};
        const float bv[8] = {b0.x, b0.y, b0.z, b0.w, b1.x, b1.y, b1.z, b1.w};
#pragma unroll
        for (int i = 0; i < 8; i++)
#pragma unroll
            for (int j = 0; j < 8; j++)
                acc[i][j] = __fmaf_rn(av[i], bv[j], acc[i][j]);
    }

    // ---- epilogue: total = inp - acc (single rounded subtract), float4 IO ----
#pragma unroll
    for (int i = 0; i < 8; i++) {
        const int m = bm + (i < 4 ? r0 + i : r1 + (i - 4));
        const float* ip = inp + (size_t)m * S_DIM;
        float* op = g_total + (size_t)m * S_DIM;
#pragma unroll
        for (int jg = 0; jg < 2; jg++) {
            const int n0 = bn + (jg == 0 ? c0 : c1);
            if (n0 < S_DIM) {   // n0 % 4 == 0 and S_DIM % 4 == 0 -> all-or-none
                float4 iv = *(const float4*)(ip + n0);
                float4 ov;
                ov.x = __fadd_rn(iv.x, -acc[i][jg * 4 + 0]);
                ov.y = __fadd_rn(iv.y, -acc[i][jg * 4 + 1]);
                ov.z = __fadd_rn(iv.z, -acc[i][jg * 4 + 2]);
                ov.w = __fadd_rn(iv.w, -acc[i][jg * 4 + 3]);
                *(float4*)(op + n0) = ov;
            }
        }
    }
}

// ---------------------------------------------------------------------------
// Kernel 2: sequential scan; thread owns TWO adjacent neurons (float2 IO).
// Software pipeline with STATIC buffer indices: two named 16-deep buffers
// (ta, tb), loop advances 32 steps, bodies fully unrolled -> everything stays
// in registers (R15's dynamic-index version was demoted to local memory).
// Per-lane math identical to validated scalar version (bitwise contract).
// ---------------------------------------------------------------------------
#define SCAN_STEP(tot_i, tt)                                                   \
    do {                                                                       \
        float2 spk;                                                            \
        {                                                                      \
            const float reset = (__fadd_rn(mem.x, -THRESH_F) > 0.f) ? 1.f : 0.f; \
            syn.x = __fmaf_rn(ALPHA_F, syn.x, (tot_i).x);                      \
            mem.x = __fmul_rn(__fmaf_rn(BETA_F, mem.x, syn.x),                 \
                              __fadd_rn(1.f, -reset));                         \
            spk.x = (__fadd_rn(mem.x, -THRESH_F) > 0.f) ? 1.f : 0.f;           \
            tr.x  = __fmaf_rn(KAPPA_F, tr.x, spk.x);                           \
        }                                                                      \
        {                                                                      \
            const float reset = (__fadd_rn(mem.y, -THRESH_F) > 0.f) ? 1.f : 0.f; \
            syn.y = __fmaf_rn(ALPHA_F, syn.y, (tot_i).y);                      \
            mem.y = __fmul_rn(__fmaf_rn(BETA_F, mem.y, syn.y),                 \
                              __fadd_rn(1.f, -reset));                         \
            spk.y = (__fadd_rn(mem.y, -THRESH_F) > 0.f) ? 1.f : 0.f;           \
            tr.y  = __fmaf_rn(KAPPA_F, tr.y, spk.y);                           \
        }                                                                      \
        __stcs(sp + (size_t)(tt) * STRIDE2, spk);                              \
        __stcs(rp + (size_t)(tt) * STRIDE2, tr);                               \
    } while (0)

__global__ __launch_bounds__(64) void scan_kernel(
    float* __restrict__ spk_out,
    float* __restrict__ tr_out)
{
    const int p = blockIdx.x * blockDim.x + threadIdx.x;   // pair index
    if (p >= BS / 2) return;

    const float2* tp = (const float2*)g_total + p;
    float2* sp = (float2*)spk_out + p;
    float2* rp = (float2*)tr_out + p;
    const int STRIDE2 = BS / 2;                            // float2 elems per t

    float2 syn = make_float2(0.f, 0.f);
    float2 mem = make_float2(0.f, 0.f);
    float2 tr  = make_float2(0.f, 0.f);

    float2 ta[16], tb[16];

    // prime: batch 0 -> ta, batch 1 -> tb
#pragma unroll
    for (int i = 0; i < 16; i++)
        ta[i] = __ldcs(tp + (size_t)i * STRIDE2);
#pragma unroll
    for (int i = 0; i < 16; i++)
        tb[i] = __ldcs(tp + (size_t)(16 + i) * STRIDE2);

#pragma unroll 1
    for (int t0 = 0; t0 < T_STEPS; t0 += 32) {
        // compute from ta; prefetch batch (t0+32) into ta afterwards
#pragma unroll
        for (int i = 0; i < 16; i++)
            SCAN_STEP(ta[i], t0 + i);
        if (t0 + 32 < T_STEPS) {
#pragma unroll
            for (int i = 0; i < 16; i++)
                ta[i] = __ldcs(tp + (size_t)(t0 + 32 + i) * STRIDE2);
        }
        // compute from tb; prefetch batch (t0+48) into tb afterwards
#pragma unroll
        for (int i = 0; i < 16; i++)
            SCAN_STEP(tb[i], t0 + 16 + i);
        if (t0 + 48 < T_STEPS) {
#pragma unroll
            for (int i = 0; i < 16; i++)
                tb[i] = __ldcs(tp + (size_t)(t0 + 48 + i) * STRIDE2);
        }
    }
}

// ---------------------------------------------------------------------------
extern "C" void kernel_launch(void* const* d_in, const int* in_sizes, int n_in,
                              void* d_out, int out_size)
{
    const float* inp = (const float*)d_in[0];   // input_signal [T, B, S]
    const float* err = (const float*)d_in[1];   // error_signal [T, B, S]
    const float* W   = (const float*)d_in[2];   // W_err [S, S]
    float* out = (float*)d_out;                 // [spks | traces]

    dim3 grid((S_DIM + BN - 1) / BN, M_ROWS / BM);   // (4, 800)
    gemm_total_kernel<<<grid, 256>>>(inp, err, W);

    scan_kernel<<<(BS / 2 + 63) / 64, 64>>>(out, out + (size_t)T_STEPS * BS);
}